// round 1
// baseline (speedup 1.0000x reference)
#include <cuda_runtime.h>

#define BB 4096
#define TT 4096
#define GAMMA 0.99f
#define CLIPV 5.0f
#define NROWBLK 64   // row blocks for column partial sums
#define THREADS 256
#define LPT 16       // elements per thread in scan (256*16 = 4096)

// γ^16 (0.99^16)
#define GAMMA16 0.8514577710948755f

__device__ float g_partial[NROWBLK * TT];
__device__ float g_colmean[TT];

// -----------------------------------------------------------------------------
// K1: per-row reverse discounted scan of weight * log_sigmoid(logits)
// one block per row, 256 threads, 16 contiguous elems/thread
// -----------------------------------------------------------------------------
__global__ __launch_bounds__(THREADS, 8)
void k1_scan(const float* __restrict__ logits,
             const float* __restrict__ weight,
             float* __restrict__ cum) {
    const int b   = blockIdx.x;
    const int tid = threadIdx.x;
    const long base = (long)b * TT + tid * LPT;

    const float4* lgp = reinterpret_cast<const float4*>(logits + base);
    const float4* wtp = reinterpret_cast<const float4*>(weight + base);

    float wr[LPT];
#pragma unroll
    for (int i = 0; i < LPT / 4; i++) {
        float4 lg = lgp[i];
        float4 wt = wtp[i];
        float xs[4] = {lg.x, lg.y, lg.z, lg.w};
        float ws[4] = {wt.x, wt.y, wt.z, wt.w};
#pragma unroll
        for (int k = 0; k < 4; k++) {
            float x  = xs[k];
            // stable log_sigmoid: min(x,0) - log1p(exp(-|x|))
            float ls = fminf(x, 0.0f) - log1pf(__expf(-fabsf(x)));
            wr[i * 4 + k] = ws[k] * ls;
        }
    }

    // thread-local reverse scan
    float c[LPT];
    float carry = 0.0f;
#pragma unroll
    for (int i = LPT - 1; i >= 0; i--) {
        carry = wr[i] + GAMMA * carry;
        c[i] = carry;
    }
    // carry == c[0] == S_j (local suffix sum with decay, zero tail)

    // cross-thread reverse inclusive scan with ratio r = γ^16
    __shared__ float s[THREADS];
    float v = carry;
    s[tid] = v;
    float f = GAMMA16;
    __syncthreads();
#pragma unroll
    for (int step = 1; step < THREADS; step <<= 1) {
        float add = (tid + step < THREADS) ? s[tid + step] : 0.0f;
        __syncthreads();
        v += f * add;
        s[tid] = v;
        f *= f;
        __syncthreads();
    }
    // s[j] = c[j*16]; tail carry into this thread's chunk = c[(j+1)*16]
    float tail = (tid + 1 < THREADS) ? s[tid + 1] : 0.0f;

    // c[k] += γ^(16-k) * tail
    float p = GAMMA;
#pragma unroll
    for (int k = LPT - 1; k >= 0; k--) {
        c[k] += p * tail;
        p *= GAMMA;
    }

    float4* cp = reinterpret_cast<float4*>(cum + base);
#pragma unroll
    for (int i = 0; i < LPT / 4; i++) {
        cp[i] = make_float4(c[i * 4 + 0], c[i * 4 + 1], c[i * 4 + 2], c[i * 4 + 3]);
    }
}

// -----------------------------------------------------------------------------
// K2a: partial column sums of (cum - baselines). grid = (16 colblk, 64 rowblk)
// -----------------------------------------------------------------------------
__global__ __launch_bounds__(THREADS, 8)
void k2_partial(const float* __restrict__ cum,
                const float* __restrict__ baselines) {
    const int col = blockIdx.x * THREADS + threadIdx.x;
    const int r0  = blockIdx.y * (BB / NROWBLK);
    float acc = 0.0f;
#pragma unroll 4
    for (int r = 0; r < BB / NROWBLK; r++) {
        long idx = (long)(r0 + r) * TT + col;
        acc += cum[idx] - baselines[idx];
    }
    g_partial[blockIdx.y * TT + col] = acc;
}

// -----------------------------------------------------------------------------
// K2b: reduce partials -> column mean
// -----------------------------------------------------------------------------
__global__ __launch_bounds__(THREADS)
void k2_reduce() {
    const int col = blockIdx.x * THREADS + threadIdx.x;
    float acc = 0.0f;
#pragma unroll 8
    for (int r = 0; r < NROWBLK; r++) acc += g_partial[r * TT + col];
    g_colmean[col] = acc * (1.0f / BB);
}

// -----------------------------------------------------------------------------
// K3: per-row objective: sum_t clip(cum - baseline - colmean) * log_probs
// one block per row
// -----------------------------------------------------------------------------
__global__ __launch_bounds__(THREADS, 8)
void k3_obj(const float* __restrict__ cum,
            const float* __restrict__ baselines,
            const float* __restrict__ log_probs,
            float* __restrict__ out) {
    const int b   = blockIdx.x;
    const int tid = threadIdx.x;
    const float4* cp = reinterpret_cast<const float4*>(cum       + (long)b * TT);
    const float4* bp = reinterpret_cast<const float4*>(baselines + (long)b * TT);
    const float4* lp = reinterpret_cast<const float4*>(log_probs + (long)b * TT);
    const float4* mp = reinterpret_cast<const float4*>(g_colmean);

    float acc = 0.0f;
#pragma unroll 4
    for (int j = tid; j < TT / 4; j += THREADS) {
        float4 c = cp[j], ba = bp[j], l = lp[j], m = mp[j];
        float a;
        a = fminf(fmaxf(c.x - ba.x - m.x, -CLIPV), CLIPV); acc = fmaf(a, l.x, acc);
        a = fminf(fmaxf(c.y - ba.y - m.y, -CLIPV), CLIPV); acc = fmaf(a, l.y, acc);
        a = fminf(fmaxf(c.z - ba.z - m.z, -CLIPV), CLIPV); acc = fmaf(a, l.z, acc);
        a = fminf(fmaxf(c.w - ba.w - m.w, -CLIPV), CLIPV); acc = fmaf(a, l.w, acc);
    }

    // block reduce
#pragma unroll
    for (int off = 16; off > 0; off >>= 1)
        acc += __shfl_down_sync(0xFFFFFFFFu, acc, off);
    __shared__ float wsum[THREADS / 32];
    if ((tid & 31) == 0) wsum[tid >> 5] = acc;
    __syncthreads();
    if (tid < 32) {
        float t = (tid < THREADS / 32) ? wsum[tid] : 0.0f;
#pragma unroll
        for (int off = 4; off > 0; off >>= 1)
            t += __shfl_down_sync(0xFFFFFFFFu, t, off);
        if (tid == 0) out[b] = t;
    }
}

// -----------------------------------------------------------------------------
extern "C" void kernel_launch(void* const* d_in, const int* in_sizes, int n_in,
                              void* d_out, int out_size) {
    const float* log_probs = (const float*)d_in[0];
    const float* logits    = (const float*)d_in[1];
    const float* weight    = (const float*)d_in[2];
    const float* baselines = (const float*)d_in[3];

    float* out = (float*)d_out;
    float* gen = out;        // [B]
    float* cum = out + BB;   // [B, T], row-major

    k1_scan<<<BB, THREADS>>>(logits, weight, cum);
    k2_partial<<<dim3(TT / THREADS, NROWBLK), THREADS>>>(cum, baselines);
    k2_reduce<<<TT / THREADS, THREADS>>>();
    k3_obj<<<BB, THREADS>>>(cum, baselines, log_probs, gen);
}

// round 3
// speedup vs baseline: 1.0175x; 1.0175x over previous
#include <cuda_runtime.h>

#define BB 4096
#define TT 4096
#define GAMMA  0.99f
#define CLIPV  5.0f
#define THREADS 256
#define LPT 16                 // columns per thread (256*16 = 4096)
#define NBLK 592               // 4 * 148 persistent blocks for K1

// gamma^16 and gamma^512 (exact repeated squaring of 0.99, double then float)
#define GAMMA16  0.8514577710948755f
#define GAMMA512 0.0058239767f
#define LOG2G   (-0.014499569695115089f)   // log2(0.99)

__device__ float g_partial[NBLK * TT];   // per-block colsum of (cum - baselines)
__device__ float g_colmean[TT];

// -----------------------------------------------------------------------------
// K1: fused reverse discounted scan + column partial sums of (cum - baselines)
// grid-stride persistent: block handles rows b, b+NBLK, ...
// thread owns columns [tid*16, tid*16+16) for every row it touches.
// -----------------------------------------------------------------------------
__global__ __launch_bounds__(THREADS, 4)
void k1_scan_fused(const float* __restrict__ logits,
                   const float* __restrict__ weight,
                   const float* __restrict__ baselines,
                   float* __restrict__ cum) {
    const int tid  = threadIdx.x;
    const int lane = tid & 31;
    const int wrp  = tid >> 5;

    __shared__ float s_w[THREADS / 32];   // per-warp totals
    __shared__ float s_s[THREADS / 32];   // scanned warp totals (inclusive)

    // gamma^(16*(31-lane)) : decay from this thread's chunk end to the start
    // of the next warp's first chunk
    const float pw = exp2f((float)(31 - lane) * 16.0f * LOG2G);

    float pacc[LPT];
#pragma unroll
    for (int k = 0; k < LPT; k++) pacc[k] = 0.0f;

    const long coff = (long)tid * LPT;

    for (int b = blockIdx.x; b < BB; b += NBLK) {
        const long base = (long)b * TT + coff;
        const float4* lgp = reinterpret_cast<const float4*>(logits + base);
        const float4* wtp = reinterpret_cast<const float4*>(weight + base);

        // load + weighted log-sigmoid
        float c[LPT];
#pragma unroll
        for (int i = 0; i < LPT / 4; i++) {
            float4 lg = lgp[i];
            float4 wt = wtp[i];
            float xs[4] = {lg.x, lg.y, lg.z, lg.w};
            float ws[4] = {wt.x, wt.y, wt.z, wt.w};
#pragma unroll
            for (int k = 0; k < 4; k++) {
                float x  = xs[k];
                float ls = fminf(x, 0.0f) - log1pf(__expf(-fabsf(x)));
                c[i * 4 + k] = ws[k] * ls;
            }
        }

        // thread-local reverse scan (zero tail)
        float carry = 0.0f;
#pragma unroll
        for (int i = LPT - 1; i >= 0; i--) {
            carry = c[i] + GAMMA * carry;
            c[i] = carry;
        }
        // carry = S = local chunk suffix value

        // warp-level reverse inclusive scan over chunk values, ratio gamma^16
        float v = carry;
        float f = GAMMA16;
#pragma unroll
        for (int step = 1; step < 32; step <<= 1) {
            float up = __shfl_down_sync(0xFFFFFFFFu, v, step);
            if (lane + step < 32) v += f * up;
            f *= f;
        }
        if (lane == 0) s_w[wrp] = v;
        __syncthreads();

        // warp 0 scans the 8 warp totals, ratio gamma^512
        if (wrp == 0 && lane < THREADS / 32) {
            float x = s_w[lane];
            float g = GAMMA512;
#pragma unroll
            for (int step = 1; step < THREADS / 32; step <<= 1) {
                float up = __shfl_down_sync(0xFFu, x, step, THREADS / 32);
                if (lane + step < THREADS / 32) x += g * up;
                g *= g;
            }
            s_s[lane] = x;
        }
        __syncthreads();

        // tail entering this thread's chunk from the right:
        //   within-warp exclusive suffix + decayed cross-warp suffix
        float ve = __shfl_down_sync(0xFFFFFFFFu, v, 1);
        if (lane == 31) ve = 0.0f;
        float Xw = (wrp + 1 < THREADS / 32) ? s_s[wrp + 1] : 0.0f;
        float T  = ve + pw * Xw;

        // fold tail into local values: c[k] += gamma^(16-k) * T
        float p = GAMMA;
#pragma unroll
        for (int k = LPT - 1; k >= 0; k--) {
            c[k] = fmaf(p, T, c[k]);
            p *= GAMMA;
        }

        // write cum, accumulate column partial of (cum - baselines)
        float4* cp = reinterpret_cast<float4*>(cum + base);
        const float4* bp = reinterpret_cast<const float4*>(baselines + base);
#pragma unroll
        for (int i = 0; i < LPT / 4; i++) {
            cp[i] = make_float4(c[i * 4 + 0], c[i * 4 + 1], c[i * 4 + 2], c[i * 4 + 3]);
            float4 ba = bp[i];
            pacc[i * 4 + 0] += c[i * 4 + 0] - ba.x;
            pacc[i * 4 + 1] += c[i * 4 + 1] - ba.y;
            pacc[i * 4 + 2] += c[i * 4 + 2] - ba.z;
            pacc[i * 4 + 3] += c[i * 4 + 3] - ba.w;
        }
        __syncthreads();   // protect s_w/s_s before next row
    }

    // one partial write per block
    float4* pp = reinterpret_cast<float4*>(g_partial + (long)blockIdx.x * TT + coff);
#pragma unroll
    for (int i = 0; i < LPT / 4; i++)
        pp[i] = make_float4(pacc[i * 4 + 0], pacc[i * 4 + 1], pacc[i * 4 + 2], pacc[i * 4 + 3]);
}

// -----------------------------------------------------------------------------
// K2: reduce partials -> column mean of (cum - baselines)
// -----------------------------------------------------------------------------
__global__ __launch_bounds__(THREADS)
void k2_reduce() {
    const int col = blockIdx.x * THREADS + threadIdx.x;
    float acc = 0.0f;
#pragma unroll 8
    for (int r = 0; r < NBLK; r++) acc += g_partial[(long)r * TT + col];
    g_colmean[col] = acc * (1.0f / BB);
}

// -----------------------------------------------------------------------------
// K3: per-row objective: sum_t clip(cum - baseline - colmean) * log_probs
// -----------------------------------------------------------------------------
__global__ __launch_bounds__(THREADS, 8)
void k3_obj(const float* __restrict__ cum,
            const float* __restrict__ baselines,
            const float* __restrict__ log_probs,
            float* __restrict__ out) {
    const int b   = blockIdx.x;
    const int tid = threadIdx.x;
    const float4* cp = reinterpret_cast<const float4*>(cum       + (long)b * TT);
    const float4* bp = reinterpret_cast<const float4*>(baselines + (long)b * TT);
    const float4* lp = reinterpret_cast<const float4*>(log_probs + (long)b * TT);
    const float4* mp = reinterpret_cast<const float4*>(g_colmean);

    float acc = 0.0f;
#pragma unroll 4
    for (int j = tid; j < TT / 4; j += THREADS) {
        float4 c = cp[j], ba = bp[j], l = lp[j], m = mp[j];
        float a;
        a = fminf(fmaxf(c.x - ba.x - m.x, -CLIPV), CLIPV); acc = fmaf(a, l.x, acc);
        a = fminf(fmaxf(c.y - ba.y - m.y, -CLIPV), CLIPV); acc = fmaf(a, l.y, acc);
        a = fminf(fmaxf(c.z - ba.z - m.z, -CLIPV), CLIPV); acc = fmaf(a, l.z, acc);
        a = fminf(fmaxf(c.w - ba.w - m.w, -CLIPV), CLIPV); acc = fmaf(a, l.w, acc);
    }

#pragma unroll
    for (int off = 16; off > 0; off >>= 1)
        acc += __shfl_down_sync(0xFFFFFFFFu, acc, off);
    __shared__ float wsum[THREADS / 32];
    if ((tid & 31) == 0) wsum[tid >> 5] = acc;
    __syncthreads();
    if (tid < 32) {
        float t = (tid < THREADS / 32) ? wsum[tid] : 0.0f;
#pragma unroll
        for (int off = 4; off > 0; off >>= 1)
            t += __shfl_down_sync(0xFFFFFFFFu, t, off);
        if (tid == 0) out[b] = t;
    }
}

// -----------------------------------------------------------------------------
extern "C" void kernel_launch(void* const* d_in, const int* in_sizes, int n_in,
                              void* d_out, int out_size) {
    const float* log_probs = (const float*)d_in[0];
    const float* logits    = (const float*)d_in[1];
    const float* weight    = (const float*)d_in[2];
    const float* baselines = (const float*)d_in[3];

    float* out = (float*)d_out;
    float* gen = out;        // [B]
    float* cum = out + BB;   // [B, T] row-major

    k1_scan_fused<<<NBLK, THREADS>>>(logits, weight, baselines, cum);
    k2_reduce<<<TT / THREADS, THREADS>>>();
    k3_obj<<<BB, THREADS>>>(cum, baselines, log_probs, gen);
}

// round 4
// speedup vs baseline: 1.0297x; 1.0119x over previous
#include <cuda_runtime.h>

#define BB 4096
#define TT 4096
#define GAMMA  0.99f
#define CLIPV  5.0f

#define THREADS 512
#define LPT 8                  // columns per thread (512*8 = 4096)
#define NW (THREADS / 32)      // 16 warps
#define NBLK 444               // 3 blocks/SM * 148 SMs, persistent

// exact powers of 0.99 (computed in double, rounded)
#define GAMMA8   0.92274469f   // 0.99^8
#define GAMMA256 0.07631496f   // 0.99^256
#define LOG2G   (-0.014499569695115089f)   // log2(0.99)

__device__ float g_partial[NBLK * TT];   // per-block colsum of (cum - baselines)
__device__ float g_colmean[TT];

// -----------------------------------------------------------------------------
// K1: fused reverse discounted scan + column partial sums of (cum - baselines)
// persistent blocks; thread owns cols [tid*8, tid*8+8) for every row it touches
// -----------------------------------------------------------------------------
__global__ __launch_bounds__(THREADS, 3)
void k1_scan_fused(const float* __restrict__ logits,
                   const float* __restrict__ weight,
                   const float* __restrict__ baselines,
                   float* __restrict__ cum) {
    const int tid  = threadIdx.x;
    const int lane = tid & 31;
    const int wrp  = tid >> 5;

    __shared__ float s_w[2][NW];   // per-warp chunk totals (double-buffered)
    __shared__ float s_s[2][NW];   // scanned warp totals (inclusive)

    // decay from this thread's chunk end to the start of the next warp:
    // gamma^(8*(31-lane))
    const float pw = exp2f((float)(31 - lane) * 8.0f * LOG2G);

    float pacc[LPT];
#pragma unroll
    for (int k = 0; k < LPT; k++) pacc[k] = 0.0f;

    const long coff = (long)tid * LPT;
    int buf = 0;

    for (int b = blockIdx.x; b < BB; b += NBLK) {
        const long base = (long)b * TT + coff;
        const float4* lgp = reinterpret_cast<const float4*>(logits + base);
        const float4* wtp = reinterpret_cast<const float4*>(weight + base);

        // load + weighted fast log-sigmoid
        float c[LPT];
#pragma unroll
        for (int i = 0; i < LPT / 4; i++) {
            float4 lg = lgp[i];
            float4 wt = wtp[i];
            float xs[4] = {lg.x, lg.y, lg.z, lg.w};
            float ws[4] = {wt.x, wt.y, wt.z, wt.w};
#pragma unroll
            for (int k = 0; k < 4; k++) {
                float x  = xs[k];
                float ls = fminf(x, 0.0f) - __logf(1.0f + __expf(-fabsf(x)));
                c[i * 4 + k] = ws[k] * ls;
            }
        }

        // thread-local reverse scan (zero tail)
        float carry = 0.0f;
#pragma unroll
        for (int i = LPT - 1; i >= 0; i--) {
            carry = c[i] + GAMMA * carry;
            c[i] = carry;
        }

        // warp-level reverse inclusive scan of chunk values, ratio gamma^8
        float v = carry;
        float f = GAMMA8;
#pragma unroll
        for (int step = 1; step < 32; step <<= 1) {
            float up = __shfl_down_sync(0xFFFFFFFFu, v, step);
            if (lane + step < 32) v += f * up;
            f *= f;
        }
        if (lane == 0) s_w[buf][wrp] = v;
        __syncthreads();

        // warp 0 scans the 16 warp totals, ratio gamma^256
        if (wrp == 0 && lane < NW) {
            float x = s_w[buf][lane];
            float g = GAMMA256;
#pragma unroll
            for (int step = 1; step < NW; step <<= 1) {
                float up = __shfl_down_sync(0xFFFFu, x, step, NW);
                if (lane + step < NW) x += g * up;
                g *= g;
            }
            s_s[buf][lane] = x;
        }
        __syncthreads();

        // tail entering this thread's chunk from the right
        float ve = __shfl_down_sync(0xFFFFFFFFu, v, 1);
        if (lane == 31) ve = 0.0f;
        float Xw = (wrp + 1 < NW) ? s_s[buf][wrp + 1] : 0.0f;
        float T  = ve + pw * Xw;

        // fold tail: c[k] += gamma^(8-k) * T
        float p = GAMMA;
#pragma unroll
        for (int k = LPT - 1; k >= 0; k--) {
            c[k] = fmaf(p, T, c[k]);
            p *= GAMMA;
        }

        // write cum, accumulate column partial of (cum - baselines)
        float4* cp = reinterpret_cast<float4*>(cum + base);
        const float4* bp = reinterpret_cast<const float4*>(baselines + base);
#pragma unroll
        for (int i = 0; i < LPT / 4; i++) {
            cp[i] = make_float4(c[i * 4 + 0], c[i * 4 + 1], c[i * 4 + 2], c[i * 4 + 3]);
            float4 ba = bp[i];
            pacc[i * 4 + 0] += c[i * 4 + 0] - ba.x;
            pacc[i * 4 + 1] += c[i * 4 + 1] - ba.y;
            pacc[i * 4 + 2] += c[i * 4 + 2] - ba.z;
            pacc[i * 4 + 3] += c[i * 4 + 3] - ba.w;
        }
        buf ^= 1;   // double-buffered smem: no trailing barrier needed
    }

    // one partial write per block
    float4* pp = reinterpret_cast<float4*>(g_partial + (long)blockIdx.x * TT + coff);
#pragma unroll
    for (int i = 0; i < LPT / 4; i++)
        pp[i] = make_float4(pacc[i * 4 + 0], pacc[i * 4 + 1], pacc[i * 4 + 2], pacc[i * 4 + 3]);
}

// -----------------------------------------------------------------------------
// K2: reduce partials -> column mean of (cum - baselines)
// -----------------------------------------------------------------------------
__global__ __launch_bounds__(256)
void k2_reduce() {
    const int col = blockIdx.x * 256 + threadIdx.x;
    float acc = 0.0f;
#pragma unroll 4
    for (int r = 0; r < NBLK; r++) acc += g_partial[(long)r * TT + col];
    g_colmean[col] = acc * (1.0f / BB);
}

// -----------------------------------------------------------------------------
// K3: per-row objective: sum_t clip(cum - baseline - colmean) * log_probs
// -----------------------------------------------------------------------------
__global__ __launch_bounds__(256, 8)
void k3_obj(const float* __restrict__ cum,
            const float* __restrict__ baselines,
            const float* __restrict__ log_probs,
            float* __restrict__ out) {
    const int b   = blockIdx.x;
    const int tid = threadIdx.x;
    const float4* cp = reinterpret_cast<const float4*>(cum       + (long)b * TT);
    const float4* bp = reinterpret_cast<const float4*>(baselines + (long)b * TT);
    const float4* lp = reinterpret_cast<const float4*>(log_probs + (long)b * TT);
    const float4* mp = reinterpret_cast<const float4*>(g_colmean);

    float acc = 0.0f;
#pragma unroll 4
    for (int j = tid; j < TT / 4; j += 256) {
        float4 c = cp[j], ba = bp[j], l = lp[j], m = mp[j];
        float a;
        a = fminf(fmaxf(c.x - ba.x - m.x, -CLIPV), CLIPV); acc = fmaf(a, l.x, acc);
        a = fminf(fmaxf(c.y - ba.y - m.y, -CLIPV), CLIPV); acc = fmaf(a, l.y, acc);
        a = fminf(fmaxf(c.z - ba.z - m.z, -CLIPV), CLIPV); acc = fmaf(a, l.z, acc);
        a = fminf(fmaxf(c.w - ba.w - m.w, -CLIPV), CLIPV); acc = fmaf(a, l.w, acc);
    }

#pragma unroll
    for (int off = 16; off > 0; off >>= 1)
        acc += __shfl_down_sync(0xFFFFFFFFu, acc, off);
    __shared__ float wsum[8];
    if ((tid & 31) == 0) wsum[tid >> 5] = acc;
    __syncthreads();
    if (tid < 32) {
        float t = (tid < 8) ? wsum[tid] : 0.0f;
#pragma unroll
        for (int off = 4; off > 0; off >>= 1)
            t += __shfl_down_sync(0xFFFFFFFFu, t, off);
        if (tid == 0) out[b] = t;
    }
}

// -----------------------------------------------------------------------------
extern "C" void kernel_launch(void* const* d_in, const int* in_sizes, int n_in,
                              void* d_out, int out_size) {
    const float* log_probs = (const float*)d_in[0];
    const float* logits    = (const float*)d_in[1];
    const float* weight    = (const float*)d_in[2];
    const float* baselines = (const float*)d_in[3];

    float* out = (float*)d_out;
    float* gen = out;        // [B]
    float* cum = out + BB;   // [B, T] row-major

    k1_scan_fused<<<NBLK, THREADS>>>(logits, weight, baselines, cum);
    k2_reduce<<<TT / 256, 256>>>();
    k3_obj<<<BB, 256>>>(cum, baselines, log_probs, gen);
}

// round 5
// speedup vs baseline: 1.3802x; 1.3404x over previous
#include <cuda_runtime.h>

#define BB 4096
#define TT 4096
#define GAMMA  0.99f
#define CLIPV  5.0f

#define THREADS 512
#define LPT 8                  // columns per thread (512*8 = 4096)
#define NW (THREADS / 32)      // 16 warps
#define NBLK 444               // 3 blocks/SM * 148 SMs — all co-resident

#define GAMMA8   0.92274469f   // 0.99^8
#define GAMMA256 0.07631496f   // 0.99^256
#define LOG2G   (-0.014499569695115089f)   // log2(0.99)

__device__ float g_partial[NBLK * TT];    // per-block colsum of (cum - baselines)
__device__ float g_colmean[TT];
__device__ unsigned g_cnt[2];             // barrier arrival counters (self-resetting)
__device__ volatile unsigned g_epoch;     // monotonic barrier epoch across replays

// epoch-based grid barrier: counters reset by completer, epoch grows monotonically
__device__ __forceinline__ void grid_barrier(unsigned* cnt, unsigned target) {
    __syncthreads();
    if (threadIdx.x == 0) {
        __threadfence();                       // release all prior writes
        if (atomicAdd(cnt, 1u) == NBLK - 1u) {
            *cnt = 0;                          // reset for next launch
            __threadfence();
            g_epoch = target;                  // release
        } else {
            while (g_epoch != target) __nanosleep(64);
            __threadfence();                   // acquire
        }
    }
    __syncthreads();
}

// -----------------------------------------------------------------------------
__global__ __launch_bounds__(THREADS, 3)
void fused_all(const float* __restrict__ log_probs,
               const float* __restrict__ logits,
               const float* __restrict__ weight,
               const float* __restrict__ baselines,
               float* __restrict__ out) {
    __shared__ float s_w[2][NW];    // phase A: per-warp chunk totals (dbl-buffered)
    __shared__ float s_s[2][NW];    // phase A: scanned warp totals
    __shared__ float s_pb[NW * 32]; // phase B reduce
    __shared__ float s_r[NW];       // phase C reduce
    __shared__ unsigned s_base;

    const int tid  = threadIdx.x;
    const int lane = tid & 31;
    const int wrp  = tid >> 5;
    const int bid  = blockIdx.x;

    if (tid == 0) s_base = g_epoch;     // read before ANY block can flip epoch
    __syncthreads();
    const unsigned base_e = s_base;

    float* gen = out;
    float* cum = out + BB;

    const float pw = exp2f((float)(31 - lane) * 8.0f * LOG2G);  // gamma^(8*(31-lane))
    const long coff = (long)tid * LPT;

    float pacc[LPT];
#pragma unroll
    for (int k = 0; k < LPT; k++) pacc[k] = 0.0f;

    // ============================ PHASE A ====================================
    // reverse discounted scan per row + column partials of (cum - baselines)
    int buf = 0;
    for (int b = bid; b < BB; b += NBLK) {
        const long base = (long)b * TT + coff;
        const float4* lgp = reinterpret_cast<const float4*>(logits + base);
        const float4* wtp = reinterpret_cast<const float4*>(weight + base);

        float c[LPT];
#pragma unroll
        for (int i = 0; i < LPT / 4; i++) {
            float4 lg = lgp[i];
            float4 wt = wtp[i];
            float xs[4] = {lg.x, lg.y, lg.z, lg.w};
            float ws[4] = {wt.x, wt.y, wt.z, wt.w};
#pragma unroll
            for (int k = 0; k < 4; k++) {
                float x  = xs[k];
                float ls = fminf(x, 0.0f) - __logf(1.0f + __expf(-fabsf(x)));
                c[i * 4 + k] = ws[k] * ls;
            }
        }

        // thread-local reverse scan
        float carry = 0.0f;
#pragma unroll
        for (int i = LPT - 1; i >= 0; i--) {
            carry = c[i] + GAMMA * carry;
            c[i] = carry;
        }

        // warp reverse inclusive scan, ratio gamma^8
        float v = carry;
        float f = GAMMA8;
#pragma unroll
        for (int step = 1; step < 32; step <<= 1) {
            float up = __shfl_down_sync(0xFFFFFFFFu, v, step);
            if (lane + step < 32) v += f * up;
            f *= f;
        }
        if (lane == 0) s_w[buf][wrp] = v;
        __syncthreads();

        // warp 0 scans 16 warp totals, ratio gamma^256
        if (wrp == 0 && lane < NW) {
            float x = s_w[buf][lane];
            float g = GAMMA256;
#pragma unroll
            for (int step = 1; step < NW; step <<= 1) {
                float up = __shfl_down_sync(0xFFFFu, x, step, NW);
                if (lane + step < NW) x += g * up;
                g *= g;
            }
            s_s[buf][lane] = x;
        }
        __syncthreads();

        float ve = __shfl_down_sync(0xFFFFFFFFu, v, 1);
        if (lane == 31) ve = 0.0f;
        float Xw = (wrp + 1 < NW) ? s_s[buf][wrp + 1] : 0.0f;
        float T  = ve + pw * Xw;

        float p = GAMMA;
#pragma unroll
        for (int k = LPT - 1; k >= 0; k--) {
            c[k] = fmaf(p, T, c[k]);
            p *= GAMMA;
        }

        float4* cp = reinterpret_cast<float4*>(cum + base);
        const float4* bp = reinterpret_cast<const float4*>(baselines + base);
#pragma unroll
        for (int i = 0; i < LPT / 4; i++) {
            cp[i] = make_float4(c[i * 4 + 0], c[i * 4 + 1], c[i * 4 + 2], c[i * 4 + 3]);
            float4 ba = bp[i];
            pacc[i * 4 + 0] += c[i * 4 + 0] - ba.x;
            pacc[i * 4 + 1] += c[i * 4 + 1] - ba.y;
            pacc[i * 4 + 2] += c[i * 4 + 2] - ba.z;
            pacc[i * 4 + 3] += c[i * 4 + 3] - ba.w;
        }
        buf ^= 1;
    }

    {
        float4* pp = reinterpret_cast<float4*>(g_partial + (long)bid * TT + coff);
#pragma unroll
        for (int i = 0; i < LPT / 4; i++)
            pp[i] = make_float4(pacc[i*4+0], pacc[i*4+1], pacc[i*4+2], pacc[i*4+3]);
    }

    grid_barrier(&g_cnt[0], base_e + 1);

    // ============================ PHASE B ====================================
    // blocks 0..127: each reduces 32 columns of g_partial -> colmean
    if (bid < 128) {
        const int c0 = bid * 32;
        float a = 0.0f;
        for (int r = wrp; r < NBLK; r += NW)          // warp w reads row r (coalesced 128B)
            a += g_partial[(long)r * TT + c0 + lane];
        s_pb[wrp * 32 + lane] = a;
        __syncthreads();
        if (wrp == 0) {
            float m = 0.0f;
#pragma unroll
            for (int k = 0; k < NW; k++) m += s_pb[k * 32 + lane];
            g_colmean[c0 + lane] = m * (1.0f / BB);
        }
    }

    grid_barrier(&g_cnt[1], base_e + 2);

    // ============================ PHASE C ====================================
    // per-row objective; block re-reads the rows it wrote (L2-warm cum)
    const float4* mp = reinterpret_cast<const float4*>(g_colmean + coff);
    const float4 m0 = mp[0], m1 = mp[1];

    for (int b = bid; b < BB; b += NBLK) {
        const long base = (long)b * TT + coff;
        const float4* cp = reinterpret_cast<const float4*>(cum       + base);
        const float4* bp = reinterpret_cast<const float4*>(baselines + base);
        const float4* lp = reinterpret_cast<const float4*>(log_probs + base);

        float4 c0v = cp[0], c1v = cp[1];
        float4 b0v = bp[0], b1v = bp[1];
        float4 l0v = lp[0], l1v = lp[1];

        float acc = 0.0f, a;
        a = fminf(fmaxf(c0v.x - b0v.x - m0.x, -CLIPV), CLIPV); acc = fmaf(a, l0v.x, acc);
        a = fminf(fmaxf(c0v.y - b0v.y - m0.y, -CLIPV), CLIPV); acc = fmaf(a, l0v.y, acc);
        a = fminf(fmaxf(c0v.z - b0v.z - m0.z, -CLIPV), CLIPV); acc = fmaf(a, l0v.z, acc);
        a = fminf(fmaxf(c0v.w - b0v.w - m0.w, -CLIPV), CLIPV); acc = fmaf(a, l0v.w, acc);
        a = fminf(fmaxf(c1v.x - b1v.x - m1.x, -CLIPV), CLIPV); acc = fmaf(a, l1v.x, acc);
        a = fminf(fmaxf(c1v.y - b1v.y - m1.y, -CLIPV), CLIPV); acc = fmaf(a, l1v.y, acc);
        a = fminf(fmaxf(c1v.z - b1v.z - m1.z, -CLIPV), CLIPV); acc = fmaf(a, l1v.z, acc);
        a = fminf(fmaxf(c1v.w - b1v.w - m1.w, -CLIPV), CLIPV); acc = fmaf(a, l1v.w, acc);

        // block reduce (fixed order -> deterministic)
#pragma unroll
        for (int off = 16; off > 0; off >>= 1)
            acc += __shfl_down_sync(0xFFFFFFFFu, acc, off);
        if (lane == 0) s_r[wrp] = acc;
        __syncthreads();
        if (tid < 32) {
            float t = (lane < NW) ? s_r[lane] : 0.0f;
#pragma unroll
            for (int off = 8; off > 0; off >>= 1)
                t += __shfl_down_sync(0xFFFFFFFFu, t, off);
            if (lane == 0) gen[b] = t;
        }
        __syncthreads();
    }
}

// -----------------------------------------------------------------------------
extern "C" void kernel_launch(void* const* d_in, const int* in_sizes, int n_in,
                              void* d_out, int out_size) {
    const float* log_probs = (const float*)d_in[0];
    const float* logits    = (const float*)d_in[1];
    const float* weight    = (const float*)d_in[2];
    const float* baselines = (const float*)d_in[3];

    fused_all<<<NBLK, THREADS>>>(log_probs, logits, weight, baselines, (float*)d_out);
}

// round 6
// speedup vs baseline: 1.5585x; 1.1292x over previous
#include <cuda_runtime.h>

#define BB 4096
#define TT 4096
#define GAMMA  0.99f
#define CLIPV  5.0f

#define THREADS 512
#define LPT 8                  // columns per thread (512*8 = 4096)
#define NW (THREADS / 32)      // 16 warps
#define NBLK 444               // 3 blocks/SM * 148 SMs — all co-resident

#define GAMMA8   0.92274469f   // 0.99^8
#define GAMMA256 0.07631496f   // 0.99^256
#define LOG2G   (-0.014499569695115089f)   // log2(0.99)

__device__ float g_partial[NBLK * TT];    // per-block colsum of (cum - baselines)
__device__ float g_colmean[TT];
__device__ unsigned g_cnt[2];             // barrier arrival counters (self-resetting)
__device__ volatile unsigned g_epoch;     // monotonic barrier epoch across replays
__device__ unsigned g_rowcnt;             // phase-C work-stealing counter (reset in phase B)

// epoch-based grid barrier
__device__ __forceinline__ void grid_barrier(unsigned* cnt, unsigned target) {
    __syncthreads();
    if (threadIdx.x == 0) {
        __threadfence();
        if (atomicAdd(cnt, 1u) == NBLK - 1u) {
            *cnt = 0;
            __threadfence();
            g_epoch = target;
        } else {
            while (g_epoch != target) __nanosleep(64);
            __threadfence();
        }
    }
    __syncthreads();
}

// -----------------------------------------------------------------------------
__global__ __launch_bounds__(THREADS, 3)
void fused_all(const float* __restrict__ log_probs,
               const float* __restrict__ logits,
               const float* __restrict__ weight,
               const float* __restrict__ baselines,
               float* __restrict__ out) {
    __shared__ float s_w[2][NW];
    __shared__ float s_s[2][NW];
    __shared__ float s_pb[NW * 32];
    __shared__ float s_r[NW];
    __shared__ unsigned s_base;
    __shared__ int s_row;

    const int tid  = threadIdx.x;
    const int lane = tid & 31;
    const int wrp  = tid >> 5;
    const int bid  = blockIdx.x;

    if (tid == 0) s_base = g_epoch;
    __syncthreads();
    const unsigned base_e = s_base;

    float* gen = out;
    float* cum = out + BB;

    const float pw = exp2f((float)(31 - lane) * 8.0f * LOG2G);
    const long coff = (long)tid * LPT;

    float pacc[LPT];
#pragma unroll
    for (int k = 0; k < LPT; k++) pacc[k] = 0.0f;

    // ============================ PHASE A ====================================
    int buf = 0;
    for (int b = bid; b < BB; b += NBLK) {
        const long base = (long)b * TT + coff;
        const float4* lgp = reinterpret_cast<const float4*>(logits + base);
        const float4* wtp = reinterpret_cast<const float4*>(weight + base);

        float c[LPT];
#pragma unroll
        for (int i = 0; i < LPT / 4; i++) {
            float4 lg = __ldcs(lgp + i);        // streaming: never reused
            float4 wt = __ldcs(wtp + i);        // streaming: never reused
            float xs[4] = {lg.x, lg.y, lg.z, lg.w};
            float ws[4] = {wt.x, wt.y, wt.z, wt.w};
#pragma unroll
            for (int k = 0; k < 4; k++) {
                float x  = xs[k];
                float ls = fminf(x, 0.0f) - __logf(1.0f + __expf(-fabsf(x)));
                c[i * 4 + k] = ws[k] * ls;
            }
        }

        // thread-local reverse scan
        float carry = 0.0f;
#pragma unroll
        for (int i = LPT - 1; i >= 0; i--) {
            carry = c[i] + GAMMA * carry;
            c[i] = carry;
        }

        // warp reverse inclusive scan, ratio gamma^8
        float v = carry;
        float f = GAMMA8;
#pragma unroll
        for (int step = 1; step < 32; step <<= 1) {
            float up = __shfl_down_sync(0xFFFFFFFFu, v, step);
            if (lane + step < 32) v += f * up;
            f *= f;
        }
        if (lane == 0) s_w[buf][wrp] = v;
        __syncthreads();

        if (wrp == 0 && lane < NW) {
            float x = s_w[buf][lane];
            float g = GAMMA256;
#pragma unroll
            for (int step = 1; step < NW; step <<= 1) {
                float up = __shfl_down_sync(0xFFFFu, x, step, NW);
                if (lane + step < NW) x += g * up;
                g *= g;
            }
            s_s[buf][lane] = x;
        }
        __syncthreads();

        float ve = __shfl_down_sync(0xFFFFFFFFu, v, 1);
        if (lane == 31) ve = 0.0f;
        float Xw = (wrp + 1 < NW) ? s_s[buf][wrp + 1] : 0.0f;
        float T  = ve + pw * Xw;

        float p = GAMMA;
#pragma unroll
        for (int k = LPT - 1; k >= 0; k--) {
            c[k] = fmaf(p, T, c[k]);
            p *= GAMMA;
        }

        float4* cp = reinterpret_cast<float4*>(cum + base);
        const float4* bp = reinterpret_cast<const float4*>(baselines + base);
#pragma unroll
        for (int i = 0; i < LPT / 4; i++) {
            cp[i] = make_float4(c[i * 4 + 0], c[i * 4 + 1], c[i * 4 + 2], c[i * 4 + 3]);
            float4 ba = bp[i];                  // default policy: may survive to phase C
            pacc[i * 4 + 0] += c[i * 4 + 0] - ba.x;
            pacc[i * 4 + 1] += c[i * 4 + 1] - ba.y;
            pacc[i * 4 + 2] += c[i * 4 + 2] - ba.z;
            pacc[i * 4 + 3] += c[i * 4 + 3] - ba.w;
        }
        buf ^= 1;
    }

    {
        float4* pp = reinterpret_cast<float4*>(g_partial + (long)bid * TT + coff);
#pragma unroll
        for (int i = 0; i < LPT / 4; i++)
            pp[i] = make_float4(pacc[i*4+0], pacc[i*4+1], pacc[i*4+2], pacc[i*4+3]);
    }

    grid_barrier(&g_cnt[0], base_e + 1);

    // ============================ PHASE B ====================================
    if (bid < 128) {
        const int c0 = bid * 32;
        float a = 0.0f;
        for (int r = wrp; r < NBLK; r += NW)
            a += g_partial[(long)r * TT + c0 + lane];
        s_pb[wrp * 32 + lane] = a;
        __syncthreads();
        if (wrp == 0) {
            float m = 0.0f;
#pragma unroll
            for (int k = 0; k < NW; k++) m += s_pb[k * 32 + lane];
            g_colmean[c0 + lane] = m * (1.0f / BB);
        }
    } else if (bid == 128 && tid == 0) {
        g_rowcnt = 0;                     // reset work-stealing counter each launch
    }

    grid_barrier(&g_cnt[1], base_e + 2);

    // ============================ PHASE C ====================================
    // descending dynamic work-stealing: newest-written rows first (L2-warm),
    // perfect load balance. gen[row] deterministic regardless of assignment.
    const float4* mp = reinterpret_cast<const float4*>(g_colmean + coff);
    const float4 m0 = mp[0], m1 = mp[1];

    for (;;) {
        if (tid == 0) s_row = (int)atomicAdd(&g_rowcnt, 1u);
        __syncthreads();
        const int r = s_row;
        if (r >= BB) break;
        const int b = BB - 1 - r;

        const long base = (long)b * TT + coff;
        const float4* cp = reinterpret_cast<const float4*>(cum       + base);
        const float4* bp = reinterpret_cast<const float4*>(baselines + base);
        const float4* lp = reinterpret_cast<const float4*>(log_probs + base);

        float4 c0v = cp[0],        c1v = cp[1];
        float4 b0v = bp[0],        b1v = bp[1];
        float4 l0v = __ldcs(lp),   l1v = __ldcs(lp + 1);   // single-use: stream

        float acc = 0.0f, a;
        a = fminf(fmaxf(c0v.x - b0v.x - m0.x, -CLIPV), CLIPV); acc = fmaf(a, l0v.x, acc);
        a = fminf(fmaxf(c0v.y - b0v.y - m0.y, -CLIPV), CLIPV); acc = fmaf(a, l0v.y, acc);
        a = fminf(fmaxf(c0v.z - b0v.z - m0.z, -CLIPV), CLIPV); acc = fmaf(a, l0v.z, acc);
        a = fminf(fmaxf(c0v.w - b0v.w - m0.w, -CLIPV), CLIPV); acc = fmaf(a, l0v.w, acc);
        a = fminf(fmaxf(c1v.x - b1v.x - m1.x, -CLIPV), CLIPV); acc = fmaf(a, l1v.x, acc);
        a = fminf(fmaxf(c1v.y - b1v.y - m1.y, -CLIPV), CLIPV); acc = fmaf(a, l1v.y, acc);
        a = fminf(fmaxf(c1v.z - b1v.z - m1.z, -CLIPV), CLIPV); acc = fmaf(a, l1v.z, acc);
        a = fminf(fmaxf(c1v.w - b1v.w - m1.w, -CLIPV), CLIPV); acc = fmaf(a, l1v.w, acc);

#pragma unroll
        for (int off = 16; off > 0; off >>= 1)
            acc += __shfl_down_sync(0xFFFFFFFFu, acc, off);
        if (lane == 0) s_r[wrp] = acc;
        __syncthreads();
        if (tid < 32) {
            float t = (lane < NW) ? s_r[lane] : 0.0f;
#pragma unroll
            for (int off = 8; off > 0; off >>= 1)
                t += __shfl_down_sync(0xFFFFFFFFu, t, off);
            if (lane == 0) gen[b] = t;
        }
        __syncthreads();   // also protects s_row for next grab
    }
}

// -----------------------------------------------------------------------------
extern "C" void kernel_launch(void* const* d_in, const int* in_sizes, int n_in,
                              void* d_out, int out_size) {
    const float* log_probs = (const float*)d_in[0];
    const float* logits    = (const float*)d_in[1];
    const float* weight    = (const float*)d_in[2];
    const float* baselines = (const float*)d_in[3];

    fused_all<<<NBLK, THREADS>>>(log_probs, logits, weight, baselines, (float*)d_out);
}